// round 11
// baseline (speedup 1.0000x reference)
#include <cuda_runtime.h>
#include <cuda_bf16.h>
#include <math.h>
#include <stdint.h>

// Problem constants
#define B_ 256
#define T_ 2048
#define C_ 12
#define K_ 4
#define L_ 8
#define FEAT_ 64
#define HID_ 128
#define NCLS_ 10
#define N2_ 1024
#define TR_ 1025
#define EPS_ 1e-5f
#define NBMAX_ 32

typedef unsigned long long ull;

// ---------------------------------------------------------------------------
// Device scratch (static; no runtime allocation)
// ---------------------------------------------------------------------------
__device__ float g_filt[K_ * TR_];
__device__ float d_modes[(size_t)K_ * B_ * C_ * T_];             // 96 MB
__device__ float d_h1[(size_t)K_ * B_ * 32 * T_];                // 256 MB
__device__ float d_h2[(size_t)K_ * B_ * 64 * T_];                // 512 MB
__device__ float d_h3[(size_t)K_ * B_ * 64 * T_];                // 512 MB
__device__ float d_psum[(size_t)K_ * 64 * B_ * NBMAX_];
__device__ float d_psq[(size_t)K_ * 64 * B_ * NBMAX_];
__device__ float d_mean[K_ * 64];
__device__ float d_rstd[K_ * 64];
__device__ float d_feats[B_ * K_ * FEAT_];
// weight pairs (w,w), layout [km][ci*KS+dk][co]
__device__ __align__(16) ull d_w2_1[K_ * 12 * 7 * 32];
__device__ __align__(16) ull d_w2_2[K_ * 32 * 5 * 64];
__device__ __align__(16) ull d_w2_3[K_ * 64 * 3 * 64];

// ---------------------------------------------------------------------------
// Packed f32x2 helpers
// ---------------------------------------------------------------------------
__device__ __forceinline__ ull pack2(float lo, float hi) {
    ull r; asm("mov.b64 %0, {%1, %2};" : "=l"(r) : "f"(lo), "f"(hi)); return r;
}
__device__ __forceinline__ ull f2u(float2 v) {
    ull r; asm("mov.b64 %0, {%1, %2};" : "=l"(r) : "f"(v.x), "f"(v.y)); return r;
}
__device__ __forceinline__ float2 u2f(ull v) {
    float2 f; asm("mov.b64 {%0, %1}, %2;" : "=f"(f.x), "=f"(f.y) : "l"(v)); return f;
}
__device__ __forceinline__ ull fma2(ull a, ull b, ull c) {
    ull d; asm("fma.rn.f32x2 %0, %1, %2, %3;" : "=l"(d) : "l"(a), "l"(b), "l"(c)); return d;
}
__device__ __forceinline__ ull add2(ull a, ull b) {
    ull d; asm("add.rn.f32x2 %0, %1, %2;" : "=l"(d) : "l"(a), "l"(b)); return d;
}

// ---------------------------------------------------------------------------
// 1. UVMD frequency-domain filters g_k(f) (scan is linear in f_hat).
// ---------------------------------------------------------------------------
__device__ __forceinline__ float softplusf(float x) {
    if (x > 20.f) return x;
    return log1pf(expf(x));
}

__global__ __launch_bounds__(128) void g_kernel(
        const float* __restrict__ log_alpha,
        const float* __restrict__ raw_tau,
        const float* __restrict__ raw_omega) {
    float om[K_];
#pragma unroll
    for (int k = 0; k < K_; k++) om[k] = 0.5f / (1.0f + expf(-raw_omega[k]));
    int f = blockIdx.x * blockDim.x + threadIdx.x;
    if (f >= TR_) return;
    float fr = 0.5f * (float)f / 1024.0f;
    float u[K_] = {0.f, 0.f, 0.f, 0.f};
    float lam = 0.f;
    for (int l = 0; l < L_; l++) {
        float tau_l = softplusf(raw_tau[l]);
        float us = u[0] + u[1] + u[2] + u[3];
        float nu[K_], ns = 0.f;
#pragma unroll
        for (int k = 0; k < K_; k++) {
            float a = expf(log_alpha[l * K_ + k]);
            float d = fr - om[k];
            float num = 1.0f - (us - u[k]) + 0.5f * lam;
            nu[k] = num / (1.0f + 2.0f * a * d * d);
            ns += nu[k];
        }
#pragma unroll
        for (int k = 0; k < K_; k++) u[k] = nu[k];
        lam += tau_l * (1.0f - ns);
    }
#pragma unroll
    for (int k = 0; k < K_; k++) g_filt[k * TR_ + f] = u[k];
}

// ---------------------------------------------------------------------------
// 2. Fused rfft -> filter -> irfft per (b,c) signal; writes modes (K,B,C,T).
// ---------------------------------------------------------------------------
__device__ __forceinline__ void fft1024(float* zr, float* zi,
                                        const float* twr, const float* twi,
                                        float dir, int tid) {
#pragma unroll
    for (int s = 0; s < 10; s++) {
        int half = 1 << s;
        int shift = 9 - s;
#pragma unroll
        for (int rep = 0; rep < 2; rep++) {
            int i = tid + rep * 256;
            int pos = i & (half - 1);
            int blk = i >> s;
            int i1 = (blk << (s + 1)) + pos;
            int i2 = i1 + half;
            int ti = pos << shift;
            float c = twr[ti];
            float sn = dir * twi[ti];
            float x2r = zr[i2], x2i = zi[i2];
            float tr = c * x2r - sn * x2i;
            float tim = sn * x2r + c * x2i;
            float x1r = zr[i1], x1i = zi[i1];
            zr[i2] = x1r - tr; zi[i2] = x1i - tim;
            zr[i1] = x1r + tr; zi[i1] = x1i + tim;
        }
        __syncthreads();
    }
}

__global__ __launch_bounds__(256) void uvmd_kernel(const float* __restrict__ x) {
    __shared__ float twr[512], twi[512];
    __shared__ float zr[N2_], zi[N2_];
    __shared__ float Xr[TR_], Xi[TR_];
    int tid = threadIdx.x;
    int sig = blockIdx.x;
    int b = sig / C_, c = sig % C_;

    for (int j = tid; j < 512; j += 256) {
        float ang = (float)M_PI * (float)j / 512.0f;
        twr[j] = cosf(ang);
        twi[j] = -sinf(ang);
    }
    const float* xb = x + (size_t)b * T_ * C_ + c;
    for (int n = tid; n < N2_; n += 256) {
        int j = __brev((unsigned)n) >> 22;
        zr[n] = xb[(size_t)(2 * j) * C_];
        zi[n] = xb[(size_t)(2 * j + 1) * C_];
    }
    __syncthreads();
    fft1024(zr, zi, twr, twi, 1.0f, tid);

    for (int k = tid; k < N2_; k += 256) {
        if (k == 0) {
            Xr[0] = zr[0] + zi[0];   Xi[0] = 0.f;
            Xr[N2_] = zr[0] - zi[0]; Xi[N2_] = 0.f;
        } else {
            float ar = zr[k], ai = zi[k];
            float br = zr[N2_ - k], bi = -zi[N2_ - k];
            float er = 0.5f * (ar + br), ei = 0.5f * (ai + bi);
            float dr = 0.5f * (ar - br), di = 0.5f * (ai - bi);
            float or_ = di, oi = -dr;
            float s_, c_;
            __sincosf(-(float)M_PI * (float)k / 1024.0f, &s_, &c_);
            Xr[k] = er + c_ * or_ - s_ * oi;
            Xi[k] = ei + s_ * or_ + c_ * oi;
        }
    }
    __syncthreads();

    const float invn = 1.0f / 1024.0f;
    for (int km = 0; km < K_; km++) {
        const float* g = g_filt + km * TR_;
        for (int n = tid; n < N2_; n += 256) {
            int k = __brev((unsigned)n) >> 22;
            float vr, vi;
            if (k == 0) {
                float y0 = g[0] * Xr[0];
                float y1 = g[N2_] * Xr[N2_];
                vr = 0.5f * (y0 + y1);
                vi = 0.5f * (y0 - y1);
            } else {
                float gk = g[k], gm = g[N2_ - k];
                float yr = gk * Xr[k], yi = gk * Xi[k];
                float mr = gm * Xr[N2_ - k], mi = -(gm * Xi[N2_ - k]);
                float er = 0.5f * (yr + mr), ei = 0.5f * (yi + mi);
                float dr = 0.5f * (yr - mr), di = 0.5f * (yi - mi);
                float s_, c_;
                __sincosf((float)M_PI * (float)k / 1024.0f, &s_, &c_);
                float or_ = c_ * dr - s_ * di;
                float oi  = s_ * dr + c_ * di;
                vr = er - oi;
                vi = ei + or_;
            }
            zr[n] = vr; zi[n] = vi;
        }
        __syncthreads();
        fft1024(zr, zi, twr, twi, -1.0f, tid);
        float* orow = d_modes + ((((size_t)km * B_ + b) * C_ + c)) * T_;
        for (int n = tid; n < N2_; n += 256) {
            float2 v = make_float2(zr[n] * invn, zi[n] * invn);
            *reinterpret_cast<float2*>(orow + 2 * n) = v;
        }
        __syncthreads();
    }
}

// ---------------------------------------------------------------------------
// 2b. Weight repack: (w,w) pairs in layout [km][ci*KS+dk][co].
// ---------------------------------------------------------------------------
template <int CIN, int COUT, int KS>
__device__ __forceinline__ void wrepack_one(const float* __restrict__ w,
                                            ull* __restrict__ dst, int i) {
    const int n = K_ * CIN * KS * COUT;
    if (i >= n) return;
    int km = i / (CIN * KS * COUT);
    int r = i % (CIN * KS * COUT);
    int tap = r / COUT;
    int co = r % COUT;
    int ci = tap / KS;
    int dk = tap % KS;
    float v = w[(((size_t)km * COUT + co) * CIN + ci) * KS + dk];
    dst[i] = pack2(v, v);
}

__global__ __launch_bounds__(256) void wprep_kernel(
    const float* __restrict__ w1, const float* __restrict__ w2,
    const float* __restrict__ w3) {
    int i = blockIdx.x * blockDim.x + threadIdx.x;
    wrepack_one<12, 32, 7>(w1, d_w2_1, i);
    wrepack_one<32, 64, 5>(w2, d_w2_2, i);
    wrepack_one<64, 64, 3>(w3, d_w2_3, i);
}

// ---------------------------------------------------------------------------
// 3. Conv1d (r5 structure): register-blocked CO=4 channels x 8 t per thread,
//    strided pair assignment (thread g owns pairs g, g+G, g+2G, g+3G),
//    f32x2 math, odd pairs packed on the ALU pipe. Fused input BN+ReLU +
//    fused BN-stat partials.
//    blockDim = 256 = (COUT/CO) * G. TILE = 8*G. gridDim = (T/TILE, B, K).
// ---------------------------------------------------------------------------
template <int CIN, int COUT, int KS, int CO, int G, int NB>
__global__ __launch_bounds__(256) void conv_kernel(
    const float* __restrict__ in, const ull* __restrict__ w2g,
    const float* __restrict__ bias,
    const float* __restrict__ bng, const float* __restrict__ bnb,
    const float* __restrict__ mean, const float* __restrict__ rstd,
    float* __restrict__ out, float* __restrict__ psum, float* __restrict__ psq,
    int apply_bn)
{
    constexpr int TT = 8;              // t positions per thread
    constexpr int TILE = G * TT;
    constexpr int PAD = KS / 2;
    constexpr int IW = TILE + KS - 1;
    constexpr int IWP = (IW + 1) & ~1;
    constexpr int NP = (KS + 1) / 2;   // even pairs needed per output pair
    constexpr int NPR = TT / 2;        // output pairs per thread (strided by G)
    static_assert((COUT / CO) * G == 256, "block size");
    __shared__ __align__(16) float s_in[CIN][IWP];
    __shared__ float s_a[CIN], s_c[CIN];

    int tx = threadIdx.x;
    int b = blockIdx.y;
    int km = blockIdx.z;
    int t0 = blockIdx.x * TILE;
    const float* inb = in + (((size_t)km * B_ + b) * CIN) * T_;

    if (apply_bn) {
        for (int ci = tx; ci < CIN; ci += 256) {
            float a = bng[km * CIN + ci] * rstd[km * 64 + ci];
            s_a[ci] = a;
            s_c[ci] = bnb[km * CIN + ci] - a * mean[km * 64 + ci];
        }
        __syncthreads();
    }
    for (int idx = tx; idx < CIN * IW; idx += 256) {
        int ci = idx / IW, tl = idx % IW;
        int t = t0 + tl - PAD;
        float v = 0.f;
        if (t >= 0 && t < T_) {
            v = inb[(size_t)ci * T_ + t];
            if (apply_bn) v = fmaxf(fmaf(s_a[ci], v, s_c[ci]), 0.f);
        }
        s_in[ci][tl] = v;
    }
    __syncthreads();

    int cog = tx / G;                  // co-group (CO channels)
    int g = tx % G;                    // strided pair lane
    int co0 = cog * CO;

    ull acc[CO][NPR];
#pragma unroll
    for (int co = 0; co < CO; co++) {
        float bsv = bias[km * COUT + co0 + co];
        ull bi = pack2(bsv, bsv);
#pragma unroll
        for (int p = 0; p < NPR; p++) acc[co][p] = bi;
    }

    const ull* wb = w2g + (size_t)km * CIN * KS * COUT + co0;
    for (int ci = 0; ci < CIN; ci++) {
        const float2* srow = reinterpret_cast<const float2*>(&s_in[ci][0]);
        float2 ef[NPR][NP];
#pragma unroll
        for (int i = 0; i < NPR; i++)
#pragma unroll
            for (int j = 0; j < NP; j++) ef[i][j] = srow[g + i * G + j];
        ull ev[NPR][NP], od[NPR][NP - 1];
#pragma unroll
        for (int i = 0; i < NPR; i++) {
#pragma unroll
            for (int j = 0; j < NP; j++) ev[i][j] = f2u(ef[i][j]);
#pragma unroll
            for (int j = 0; j < NP - 1; j++)
                od[i][j] = pack2(ef[i][j].y, ef[i][j + 1].x);
        }
        const ull* wci = wb + (size_t)ci * KS * COUT;
#pragma unroll
        for (int dk = 0; dk < KS; dk++) {
            ull w[CO];
#pragma unroll
            for (int h = 0; h < CO / 2; h++) {
                ulonglong2 wp = __ldg(reinterpret_cast<const ulonglong2*>(
                    wci + (size_t)dk * COUT + 2 * h));
                w[2 * h] = wp.x;
                w[2 * h + 1] = wp.y;
            }
#pragma unroll
            for (int co = 0; co < CO; co++)
#pragma unroll
                for (int i = 0; i < NPR; i++) {
                    ull xv = (dk & 1) ? od[i][(dk - 1) / 2] : ev[i][dk / 2];
                    acc[co][i] = fma2(xv, w[co], acc[co][i]);
                }
        }
    }

    // epilogue: store pre-BN outputs + per-channel stats partials
#pragma unroll
    for (int co = 0; co < CO; co++) {
        float* op = out + (((size_t)km * B_ + b) * COUT + co0 + co) * T_ + t0;
        ull ssum = 0, qsum = 0;        // ull 0 == packed (0.f, 0.f)
#pragma unroll
        for (int i = 0; i < NPR; i++) {
            float2 o = u2f(acc[co][i]);
            *reinterpret_cast<float2*>(op + 2 * (g + i * G)) = o;
            ssum = add2(ssum, acc[co][i]);
            qsum = fma2(acc[co][i], acc[co][i], qsum);
        }
        float2 fs = u2f(ssum), fq = u2f(qsum);
        float s = fs.x + fs.y;
        float q = fq.x + fq.y;
#pragma unroll
        for (int o = G / 2; o > 0; o >>= 1) {
            s += __shfl_down_sync(0xffffffffu, s, o, G);
            q += __shfl_down_sync(0xffffffffu, q, o, G);
        }
        if (g == 0) {
            size_t pidx = ((size_t)(km * COUT + co0 + co) * B_ + b) * NB
                          + blockIdx.x;
            psum[pidx] = s;
            psq[pidx] = q;
        }
    }
}

// ---------------------------------------------------------------------------
// 4. BN statistics finalize: one block per (km, ch), sums B*nblk partials.
// ---------------------------------------------------------------------------
__global__ __launch_bounds__(256) void stats_fin_kernel(int Cout, int nblk) {
    int co = blockIdx.x, km = blockIdx.y;
    int tid = threadIdx.x;
    const float* ps = d_psum + (size_t)(km * Cout + co) * B_ * nblk;
    const float* pq = d_psq + (size_t)(km * Cout + co) * B_ * nblk;
    float s = 0.f, q = 0.f;
    for (int i = tid; i < B_ * nblk; i += 256) {
        s += ps[i];
        q += pq[i];
    }
    __shared__ float r1[256], r2[256];
    r1[tid] = s; r2[tid] = q;
    __syncthreads();
    for (int o = 128; o > 0; o >>= 1) {
        if (tid < o) { r1[tid] += r1[tid + o]; r2[tid] += r2[tid + o]; }
        __syncthreads();
    }
    if (tid == 0) {
        float cnt = (float)B_ * (float)T_;
        float m = r1[0] / cnt;
        float v = r2[0] / cnt - m * m;
        d_mean[km * 64 + co] = m;
        d_rstd[km * 64 + co] = rsqrtf(v + EPS_);
    }
}

// ---------------------------------------------------------------------------
// 5. BN+ReLU + mean-pool over T -> feats (B, K*FEAT)
// ---------------------------------------------------------------------------
__global__ __launch_bounds__(256) void pool_kernel(
    const float* __restrict__ h,
    const float* __restrict__ bng, const float* __restrict__ bnb) {
    int co = blockIdx.x, b = blockIdx.y, km = blockIdx.z;
    int tid = threadIdx.x;
    float a = bng[km * FEAT_ + co] * d_rstd[km * 64 + co];
    float cc = bnb[km * FEAT_ + co] - a * d_mean[km * 64 + co];
    const float* row = h + (((size_t)km * B_ + b) * FEAT_ + co) * T_;
    float s = 0.f;
    for (int t = tid; t < T_; t += 256)
        s += fmaxf(fmaf(a, row[t], cc), 0.f);
    __shared__ float r[256];
    r[tid] = s;
    __syncthreads();
    for (int o = 128; o > 0; o >>= 1) {
        if (tid < o) r[tid] += r[tid + o];
        __syncthreads();
    }
    if (tid == 0)
        d_feats[(size_t)b * (K_ * FEAT_) + km * FEAT_ + co] = r[0] * (1.0f / T_);
}

// ---------------------------------------------------------------------------
// 6. Classifier: relu(fused @ fc1^T + b1) @ fc2^T + b2
// ---------------------------------------------------------------------------
__global__ __launch_bounds__(128) void classifier_kernel(
    const float* __restrict__ w1, const float* __restrict__ b1,
    const float* __restrict__ w2, const float* __restrict__ b2,
    float* __restrict__ out) {
    int b = blockIdx.x;
    int j = threadIdx.x;
    __shared__ float sf[K_ * FEAT_];
    __shared__ float sh[HID_];
    for (int i = j; i < K_ * FEAT_; i += 128) sf[i] = d_feats[(size_t)b * (K_ * FEAT_) + i];
    __syncthreads();
    float a = b1[j];
    const float* wr = w1 + (size_t)j * (K_ * FEAT_);
#pragma unroll 8
    for (int i = 0; i < K_ * FEAT_; i++) a = fmaf(sf[i], wr[i], a);
    sh[j] = fmaxf(a, 0.f);
    __syncthreads();
    if (j < NCLS_) {
        float o = b2[j];
        const float* w2r = w2 + (size_t)j * HID_;
#pragma unroll 8
        for (int i = 0; i < HID_; i++) o = fmaf(sh[i], w2r[i], o);
        out[b * NCLS_ + j] = o;
    }
}

// ---------------------------------------------------------------------------
// Launch
// ---------------------------------------------------------------------------
extern "C" void kernel_launch(void* const* d_in, const int* in_sizes, int n_in,
                              void* d_out, int out_size) {
    const float* x         = (const float*)d_in[0];
    const float* log_alpha = (const float*)d_in[1];
    const float* raw_tau   = (const float*)d_in[2];
    const float* raw_omega = (const float*)d_in[3];
    const float* conv_w1   = (const float*)d_in[4];
    const float* conv_b1   = (const float*)d_in[5];
    const float* bn_g1     = (const float*)d_in[6];
    const float* bn_b1     = (const float*)d_in[7];
    const float* conv_w2   = (const float*)d_in[8];
    const float* conv_b2   = (const float*)d_in[9];
    const float* bn_g2     = (const float*)d_in[10];
    const float* bn_b2     = (const float*)d_in[11];
    const float* conv_w3   = (const float*)d_in[12];
    const float* conv_b3   = (const float*)d_in[13];
    const float* bn_g3     = (const float*)d_in[14];
    const float* bn_b3     = (const float*)d_in[15];
    const float* fc1_w     = (const float*)d_in[16];
    const float* fc1_b     = (const float*)d_in[17];
    const float* fc2_w     = (const float*)d_in[18];
    const float* fc2_b     = (const float*)d_in[19];
    float* out = (float*)d_out;

    float *p_modes, *p_h1, *p_h2, *p_h3, *p_mean, *p_rstd, *p_psum, *p_psq;
    ull *p_w21, *p_w22, *p_w23;
    cudaGetSymbolAddress((void**)&p_modes, d_modes);
    cudaGetSymbolAddress((void**)&p_h1, d_h1);
    cudaGetSymbolAddress((void**)&p_h2, d_h2);
    cudaGetSymbolAddress((void**)&p_h3, d_h3);
    cudaGetSymbolAddress((void**)&p_mean, d_mean);
    cudaGetSymbolAddress((void**)&p_rstd, d_rstd);
    cudaGetSymbolAddress((void**)&p_psum, d_psum);
    cudaGetSymbolAddress((void**)&p_psq, d_psq);
    cudaGetSymbolAddress((void**)&p_w21, d_w2_1);
    cudaGetSymbolAddress((void**)&p_w22, d_w2_2);
    cudaGetSymbolAddress((void**)&p_w23, d_w2_3);

    // #1 UVMD filters
    g_kernel<<<(TR_ + 127) / 128, 128>>>(log_alpha, raw_tau, raw_omega);
    // #2 FFT -> filter -> iFFT -> modes
    uvmd_kernel<<<B_ * C_, 256>>>(x);
    // #3 weight repack
    wprep_kernel<<<(K_ * 64 * 64 * 3 + 255) / 256, 256>>>(conv_w1, conv_w2, conv_w3);

    // #4 conv1: 12 -> 32, k=7, CO=4, G=32 (TILE=256, NB=8)  <-- ncu capture
    conv_kernel<12, 32, 7, 4, 32, 8><<<dim3(8, B_, K_), 256>>>(
        p_modes, p_w21, conv_b1, nullptr, nullptr, nullptr, nullptr,
        p_h1, p_psum, p_psq, 0);
    // #5 finalize BN1
    stats_fin_kernel<<<dim3(32, K_), 256>>>(32, 8);
    // #6 conv2: 32 -> 64, k=5, CO=4, G=16 (TILE=128, NB=16)  [r5-proven]
    conv_kernel<32, 64, 5, 4, 16, 16><<<dim3(16, B_, K_), 256>>>(
        p_h1, p_w22, conv_b2, bn_g1, bn_b1, p_mean, p_rstd,
        p_h2, p_psum, p_psq, 1);
    stats_fin_kernel<<<dim3(64, K_), 256>>>(64, 16);
    // conv3: 64 -> 64, k=3, CO=4, G=16 (TILE=128, NB=16)  [r5-proven]
    conv_kernel<64, 64, 3, 4, 16, 16><<<dim3(16, B_, K_), 256>>>(
        p_h2, p_w23, conv_b3, bn_g2, bn_b2, p_mean, p_rstd,
        p_h3, p_psum, p_psq, 1);
    stats_fin_kernel<<<dim3(64, K_), 256>>>(64, 16);
    // BN3+ReLU + mean pool
    pool_kernel<<<dim3(FEAT_, B_, K_), 256>>>(p_h3, bn_g3, bn_b3);
    // classifier
    classifier_kernel<<<B_, HID_>>>(fc1_w, fc1_b, fc2_w, fc2_b, out);
}

// round 13
// speedup vs baseline: 1.4081x; 1.4081x over previous
#include <cuda_runtime.h>
#include <cuda_bf16.h>
#include <math.h>
#include <stdint.h>

#define B_ 256
#define T_ 2048
#define C_ 12
#define K_ 4
#define L_ 8
#define FEAT_ 64
#define HID_ 128
#define NCLS_ 10
#define N2_ 1024
#define TR_ 1025
#define EPS_ 1e-5f
#define NBMAX_ 128

typedef unsigned long long ull;

__device__ float g_filt[K_ * TR_];
__device__ float d_modes[(size_t)K_ * B_ * C_ * T_];
__device__ float d_h1[(size_t)K_ * B_ * 32 * T_];
__device__ float d_h2[(size_t)K_ * B_ * 64 * T_];
__device__ float d_h3[(size_t)K_ * B_ * 64 * T_];
__device__ float d_psum[(size_t)K_ * 64 * B_ * NBMAX_];
__device__ float d_psq[(size_t)K_ * 64 * B_ * NBMAX_];
__device__ float d_mean[K_ * 64];
__device__ float d_rstd[K_ * 64];
__device__ float d_feats[B_ * K_ * FEAT_];
__device__ __align__(16) ull d_w2_1[K_ * 12 * 7 * 32];
// mma weight images: [km][dk][half][co=64][ci padded to CIN+8] bf16 (hi,lo)
__device__ __align__(16) __nv_bfloat16 d_wimg2[K_ * 5 * 2 * 64 * 40];
__device__ __align__(16) __nv_bfloat16 d_wimg3[K_ * 3 * 2 * 64 * 72];

__device__ __forceinline__ ull pack2(float lo, float hi) {
    ull r; asm("mov.b64 %0, {%1, %2};" : "=l"(r) : "f"(lo), "f"(hi)); return r;
}
__device__ __forceinline__ ull f2u(float2 v) {
    ull r; asm("mov.b64 %0, {%1, %2};" : "=l"(r) : "f"(v.x), "f"(v.y)); return r;
}
__device__ __forceinline__ float2 u2f(ull v) {
    float2 f; asm("mov.b64 {%0, %1}, %2;" : "=f"(f.x), "=f"(f.y) : "l"(v)); return f;
}
__device__ __forceinline__ ull fma2(ull a, ull b, ull c) {
    ull d; asm("fma.rn.f32x2 %0, %1, %2, %3;" : "=l"(d) : "l"(a), "l"(b), "l"(c)); return d;
}
__device__ __forceinline__ ull add2(ull a, ull b) {
    ull d; asm("add.rn.f32x2 %0, %1, %2;" : "=l"(d) : "l"(a), "l"(b)); return d;
}
__device__ __forceinline__ uint32_t smem_u32(const void* p) {
    uint32_t a;
    asm("{ .reg .u64 t; cvta.to.shared.u64 t, %1; cvt.u32.u64 %0, t; }" : "=r"(a) : "l"(p));
    return a;
}
__device__ __forceinline__ void ldsm4(uint32_t* a, uint32_t addr) {
    asm volatile("ldmatrix.sync.aligned.m8n8.x4.shared.b16 {%0,%1,%2,%3}, [%4];"
        : "=r"(a[0]), "=r"(a[1]), "=r"(a[2]), "=r"(a[3]) : "r"(addr));
}
__device__ __forceinline__ void ldsm2(uint32_t* b, uint32_t addr) {
    asm volatile("ldmatrix.sync.aligned.m8n8.x2.shared.b16 {%0,%1}, [%2];"
        : "=r"(b[0]), "=r"(b[1]) : "r"(addr));
}
__device__ __forceinline__ void mma16816(float* d, const uint32_t* a, const uint32_t* b) {
    asm volatile(
        "mma.sync.aligned.m16n8k16.row.col.f32.bf16.bf16.f32 "
        "{%0,%1,%2,%3}, {%4,%5,%6,%7}, {%8,%9}, {%0,%1,%2,%3};"
        : "+f"(d[0]), "+f"(d[1]), "+f"(d[2]), "+f"(d[3])
        : "r"(a[0]), "r"(a[1]), "r"(a[2]), "r"(a[3]), "r"(b[0]), "r"(b[1]));
}

// ---- 1. UVMD filters ----
__device__ __forceinline__ float softplusf(float x) {
    if (x > 20.f) return x;
    return log1pf(expf(x));
}
__global__ __launch_bounds__(128) void g_kernel(
        const float* __restrict__ la, const float* __restrict__ rt,
        const float* __restrict__ ro) {
    float om[K_];
#pragma unroll
    for (int k = 0; k < K_; k++) om[k] = 0.5f / (1.0f + expf(-ro[k]));
    int f = blockIdx.x * blockDim.x + threadIdx.x;
    if (f >= TR_) return;
    float fr = 0.5f * (float)f / 1024.0f;
    float u[K_] = {0.f, 0.f, 0.f, 0.f};
    float lam = 0.f;
    for (int l = 0; l < L_; l++) {
        float tau_l = softplusf(rt[l]);
        float us = u[0] + u[1] + u[2] + u[3];
        float nu[K_], ns = 0.f;
#pragma unroll
        for (int k = 0; k < K_; k++) {
            float a = expf(la[l * K_ + k]);
            float d = fr - om[k];
            nu[k] = (1.0f - (us - u[k]) + 0.5f * lam) / (1.0f + 2.0f * a * d * d);
            ns += nu[k];
        }
#pragma unroll
        for (int k = 0; k < K_; k++) u[k] = nu[k];
        lam += tau_l * (1.0f - ns);
    }
#pragma unroll
    for (int k = 0; k < K_; k++) g_filt[k * TR_ + f] = u[k];
}

// ---- 2. UVMD FFT ----
__device__ __forceinline__ void fft1024(float* zr, float* zi, const float* twr,
                                        const float* twi, float dir, int tid) {
#pragma unroll
    for (int s = 0; s < 10; s++) {
        int half = 1 << s, shift = 9 - s;
#pragma unroll
        for (int rep = 0; rep < 2; rep++) {
            int i = tid + rep * 256;
            int pos = i & (half - 1);
            int i1 = ((i >> s) << (s + 1)) + pos;
            int i2 = i1 + half;
            int ti = pos << shift;
            float c = twr[ti], sn = dir * twi[ti];
            float x2r = zr[i2], x2i = zi[i2];
            float tr = c * x2r - sn * x2i, tim = sn * x2r + c * x2i;
            float x1r = zr[i1], x1i = zi[i1];
            zr[i2] = x1r - tr; zi[i2] = x1i - tim;
            zr[i1] = x1r + tr; zi[i1] = x1i + tim;
        }
        __syncthreads();
    }
}
__global__ __launch_bounds__(256) void uvmd_kernel(const float* __restrict__ x) {
    __shared__ float twr[512], twi[512];
    __shared__ float zr[N2_], zi[N2_];
    __shared__ float Xr[TR_], Xi[TR_];
    int tid = threadIdx.x;
    int b = blockIdx.x / C_, c = blockIdx.x % C_;
    for (int j = tid; j < 512; j += 256) {
        float ang = (float)M_PI * (float)j / 512.0f;
        twr[j] = cosf(ang); twi[j] = -sinf(ang);
    }
    const float* xb = x + (size_t)b * T_ * C_ + c;
    for (int n = tid; n < N2_; n += 256) {
        int j = __brev((unsigned)n) >> 22;
        zr[n] = xb[(size_t)(2 * j) * C_];
        zi[n] = xb[(size_t)(2 * j + 1) * C_];
    }
    __syncthreads();
    fft1024(zr, zi, twr, twi, 1.0f, tid);
    for (int k = tid; k < N2_; k += 256) {
        if (k == 0) {
            Xr[0] = zr[0] + zi[0]; Xi[0] = 0.f;
            Xr[N2_] = zr[0] - zi[0]; Xi[N2_] = 0.f;
        } else {
            float ar = zr[k], ai = zi[k];
            float br = zr[N2_ - k], bi = -zi[N2_ - k];
            float er = 0.5f * (ar + br), ei = 0.5f * (ai + bi);
            float dr = 0.5f * (ar - br), di = 0.5f * (ai - bi);
            float or_ = di, oi = -dr, s_, c_;
            __sincosf(-(float)M_PI * (float)k / 1024.0f, &s_, &c_);
            Xr[k] = er + c_ * or_ - s_ * oi;
            Xi[k] = ei + s_ * or_ + c_ * oi;
        }
    }
    __syncthreads();
    const float invn = 1.0f / 1024.0f;
    for (int km = 0; km < K_; km++) {
        const float* g = g_filt + km * TR_;
        for (int n = tid; n < N2_; n += 256) {
            int k = __brev((unsigned)n) >> 22;
            float vr, vi;
            if (k == 0) {
                float y0 = g[0] * Xr[0], y1 = g[N2_] * Xr[N2_];
                vr = 0.5f * (y0 + y1); vi = 0.5f * (y0 - y1);
            } else {
                float gk = g[k], gm = g[N2_ - k];
                float yr = gk * Xr[k], yi = gk * Xi[k];
                float mr = gm * Xr[N2_ - k], mi = -(gm * Xi[N2_ - k]);
                float er = 0.5f * (yr + mr), ei = 0.5f * (yi + mi);
                float dr = 0.5f * (yr - mr), di = 0.5f * (yi - mi);
                float s_, c_;
                __sincosf((float)M_PI * (float)k / 1024.0f, &s_, &c_);
                vr = er - (s_ * dr + c_ * di);
                vi = ei + (c_ * dr - s_ * di);
            }
            zr[n] = vr; zi[n] = vi;
        }
        __syncthreads();
        fft1024(zr, zi, twr, twi, -1.0f, tid);
        float* orow = d_modes + ((((size_t)km * B_ + b) * C_ + c)) * T_;
        for (int n = tid; n < N2_; n += 256)
            *reinterpret_cast<float2*>(orow + 2 * n) =
                make_float2(zr[n] * invn, zi[n] * invn);
        __syncthreads();
    }
}

// ---- 2b. weight prep ----
template <int CIN, int KS, int CINP>
__device__ __forceinline__ void wimg_one(const float* __restrict__ w,
                                         __nv_bfloat16* __restrict__ img, int i) {
    const int n = K_ * KS * 2 * 64 * CINP;
    if (i >= n) return;
    int ci = i % CINP;
    int r = i / CINP;
    int co = r % 64; r /= 64;
    int half = r % 2; r /= 2;
    int dk = r % KS;
    int km = r / KS;
    float f = (ci < CIN) ? w[(((size_t)km * 64 + co) * CIN + ci) * KS + dk] : 0.f;
    __nv_bfloat16 hi = __float2bfloat16(f);
    img[i] = half ? __float2bfloat16(f - __bfloat162float(hi)) : hi;
}
__global__ __launch_bounds__(256) void wprep_kernel(
    const float* __restrict__ w1, const float* __restrict__ w2,
    const float* __restrict__ w3) {
    int i = blockIdx.x * blockDim.x + threadIdx.x;
    if (i < K_ * 12 * 7 * 32) {
        int km = i / (12 * 7 * 32), r = i % (12 * 7 * 32);
        int tap = r / 32, co = r % 32, ci = tap / 7, dk = tap % 7;
        float v = w1[(((size_t)km * 32 + co) * 12 + ci) * 7 + dk];
        d_w2_1[i] = pack2(v, v);
    }
    wimg_one<32, 5, 40>(w2, d_wimg2, i);
    wimg_one<64, 3, 72>(w3, d_wimg3, i);
}

// ---- 3. conv1 (CUDA core, r10-proven) ----
template <int CIN, int COUT, int KS, int CO, int G, int NB>
__global__ __launch_bounds__(256) void conv_kernel(
    const float* __restrict__ in, const ull* __restrict__ w2g,
    const float* __restrict__ bias,
    float* __restrict__ out, float* __restrict__ psum, float* __restrict__ psq)
{
    constexpr int TT = 8, TILE = G * TT, PAD = KS / 2;
    constexpr int IW = TILE + KS - 1, IWP = (IW + 1) & ~1;
    constexpr int NP = (KS + 1) / 2, NPR = TT / 2;
    __shared__ __align__(16) float s_in[CIN][IWP];
    int tx = threadIdx.x, b = blockIdx.y, km = blockIdx.z;
    int t0 = blockIdx.x * TILE;
    const float* inb = in + (((size_t)km * B_ + b) * CIN) * T_;
    for (int idx = tx; idx < CIN * IW; idx += 256) {
        int ci = idx / IW, tl = idx % IW;
        int t = t0 + tl - PAD;
        s_in[ci][tl] = (t >= 0 && t < T_) ? inb[(size_t)ci * T_ + t] : 0.f;
    }
    __syncthreads();
    int cog = tx / G, g = tx % G, co0 = cog * CO;
    ull acc[CO][NPR];
#pragma unroll
    for (int co = 0; co < CO; co++) {
        float bs = bias[km * COUT + co0 + co];
        ull bi = pack2(bs, bs);
#pragma unroll
        for (int p = 0; p < NPR; p++) acc[co][p] = bi;
    }
    const ull* wb = w2g + (size_t)km * CIN * KS * COUT + co0;
    for (int ci = 0; ci < CIN; ci++) {
        const float2* srow = reinterpret_cast<const float2*>(&s_in[ci][0]);
        float2 ef[NPR][NP];
#pragma unroll
        for (int i = 0; i < NPR; i++)
#pragma unroll
            for (int j = 0; j < NP; j++) ef[i][j] = srow[g + i * G + j];
        ull ev[NPR][NP], od[NPR][NP - 1];
#pragma unroll
        for (int i = 0; i < NPR; i++) {
#pragma unroll
            for (int j = 0; j < NP; j++) ev[i][j] = f2u(ef[i][j]);
#pragma unroll
            for (int j = 0; j < NP - 1; j++)
                od[i][j] = pack2(ef[i][j].y, ef[i][j + 1].x);
        }
        const ull* wci = wb + (size_t)ci * KS * COUT;
#pragma unroll
        for (int dk = 0; dk < KS; dk++) {
            ull w[CO];
#pragma unroll
            for (int h = 0; h < CO / 2; h++) {
                ulonglong2 wp = __ldg(reinterpret_cast<const ulonglong2*>(
                    wci + (size_t)dk * COUT + 2 * h));
                w[2 * h] = wp.x; w[2 * h + 1] = wp.y;
            }
#pragma unroll
            for (int co = 0; co < CO; co++)
#pragma unroll
                for (int i = 0; i < NPR; i++) {
                    ull xv = (dk & 1) ? od[i][(dk - 1) / 2] : ev[i][dk / 2];
                    acc[co][i] = fma2(xv, w[co], acc[co][i]);
                }
        }
    }
#pragma unroll
    for (int co = 0; co < CO; co++) {
        float* op = out + (((size_t)km * B_ + b) * COUT + co0 + co) * T_ + t0;
        ull ss = 0, qq = 0;
#pragma unroll
        for (int i = 0; i < NPR; i++) {
            *reinterpret_cast<float2*>(op + 2 * (g + i * G)) = u2f(acc[co][i]);
            ss = add2(ss, acc[co][i]);
            qq = fma2(acc[co][i], acc[co][i], qq);
        }
        float2 fs = u2f(ss), fq = u2f(qq);
        float s = fs.x + fs.y, q = fq.x + fq.y;
#pragma unroll
        for (int o = G / 2; o > 0; o >>= 1) {
            s += __shfl_down_sync(0xffffffffu, s, o, G);
            q += __shfl_down_sync(0xffffffffu, q, o, G);
        }
        if (g == 0) {
            size_t pi = ((size_t)(km * COUT + co0 + co) * B_ + b) * NB + blockIdx.x;
            psum[pi] = s; psq[pi] = q;
        }
    }
}

// ---- 3b. conv2/conv3 via mma.sync bf16 hi/lo split ----
// CTA = one 128t x 64co tile of one (km,b). 8 warps; warp w owns t rows
// 16w..16w+15 x all 64 co (8 n-frags of m16n8k16).
template <int CIN, int KS>
__global__ __launch_bounds__(256) void conv_mma_kernel(
    const float* __restrict__ in, const __nv_bfloat16* __restrict__ wimg,
    const float* __restrict__ bias,
    const float* __restrict__ bng, const float* __restrict__ bnb,
    float* __restrict__ out, float* __restrict__ psum, float* __restrict__ psq)
{
    constexpr int PAD = KS / 2, NROW = 136, CINP = CIN + 8, ROWB = CINP * 2;
    constexpr int XB = NROW * ROWB;            // bytes per X half
    constexpr int WSEG = 64 * ROWB;            // bytes per (dk,half) W tile
    constexpr int OFF_XL = XB, OFF_W = 2 * XB;
    constexpr int OFF_SA = OFF_W + KS * 2 * WSEG;
    constexpr int NCC = CIN / 16;
    extern __shared__ __align__(16) char smem[];
    uint32_t sb = smem_u32(smem);
    int tid = threadIdx.x, w = tid >> 5, lane = tid & 31;
    int b = blockIdx.y, km = blockIdx.z, bx = blockIdx.x;
    int t0 = bx * 128;

    float* s_a = reinterpret_cast<float*>(smem + OFF_SA);
    float* s_c = s_a + CIN;
    for (int ci = tid; ci < CIN; ci += 256) {
        float a = bng[km * CIN + ci] * d_rstd[km * 64 + ci];
        s_a[ci] = a;
        s_c[ci] = bnb[km * CIN + ci] - a * d_mean[km * 64 + ci];
    }
    __syncthreads();
    // X fill: BN+ReLU + hi/lo split; rows r = local t (global t0+r-PAD)
    const float* inb = in + (((size_t)km * B_ + b) * CIN) * T_;
    for (int idx = tid; idx < CIN * NROW; idx += 256) {
        int ci = idx / NROW, r = idx % NROW;
        int t = t0 + r - PAD;
        float v = 0.f;
        if (t >= 0 && t < T_)
            v = fmaxf(fmaf(s_a[ci], inb[(size_t)ci * T_ + t], s_c[ci]), 0.f);
        __nv_bfloat16 hi = __float2bfloat16(v);
        __nv_bfloat16 lo = __float2bfloat16(v - __bfloat162float(hi));
        *reinterpret_cast<__nv_bfloat16*>(smem + r * ROWB + ci * 2) = hi;
        *reinterpret_cast<__nv_bfloat16*>(smem + OFF_XL + r * ROWB + ci * 2) = lo;
    }
    // W copy (pre-split, pre-padded images)
    {
        const uint4* src = reinterpret_cast<const uint4*>(
            reinterpret_cast<const char*>(wimg) + (size_t)km * KS * 2 * WSEG);
        uint4* dst = reinterpret_cast<uint4*>(smem + OFF_W);
        for (int i = tid; i < KS * 2 * WSEG / 16; i += 256) dst[i] = src[i];
    }
    __syncthreads();

    int m0 = w * 16;
    float acc[8][4];
#pragma unroll
    for (int j = 0; j < 8; j++)
#pragma unroll
        for (int p = 0; p < 4; p++) acc[j][p] = 0.f;

    uint32_t aoff = (uint32_t)((lane & 15) * ROWB + (lane >> 4) * 16);
    uint32_t boff = (uint32_t)((lane & 7) * ROWB + ((lane >> 3) & 1) * 16);
    for (int cc = 0; cc < NCC; cc++) {
#pragma unroll
        for (int dk = 0; dk < KS; dk++) {
            uint32_t ab = sb + (uint32_t)((m0 + dk) * ROWB + cc * 32) + aoff;
            uint32_t ah[4], al[4];
            ldsm4(ah, ab);
            ldsm4(al, ab + XB);
            uint32_t wbase = sb + OFF_W + (uint32_t)(dk * 2 * WSEG + cc * 32) + boff;
#pragma unroll
            for (int j = 0; j < 8; j++) {
                uint32_t bh[2], bl[2];
                ldsm2(bh, wbase + j * 8 * ROWB);
                ldsm2(bl, wbase + WSEG + j * 8 * ROWB);
                mma16816(acc[j], ah, bh);
                mma16816(acc[j], ah, bl);
                mma16816(acc[j], al, bh);
            }
        }
    }

    // bias + stats (register-level, deterministic shfl tree)
    int cbase = 2 * (lane & 3);
#pragma unroll
    for (int j = 0; j < 8; j++) {
        float b0 = __ldg(&bias[km * 64 + 8 * j + cbase]);
        float b1 = __ldg(&bias[km * 64 + 8 * j + cbase + 1]);
        acc[j][0] += b0; acc[j][1] += b1;
        acc[j][2] += b0; acc[j][3] += b1;
        float s0 = acc[j][0] + acc[j][2];
        float s1 = acc[j][1] + acc[j][3];
        float q0 = acc[j][0] * acc[j][0] + acc[j][2] * acc[j][2];
        float q1 = acc[j][1] * acc[j][1] + acc[j][3] * acc[j][3];
#pragma unroll
        for (int o = 16; o >= 4; o >>= 1) {
            s0 += __shfl_down_sync(0xffffffffu, s0, o);
            s1 += __shfl_down_sync(0xffffffffu, s1, o);
            q0 += __shfl_down_sync(0xffffffffu, q0, o);
            q1 += __shfl_down_sync(0xffffffffu, q1, o);
        }
        if (lane < 4) {
            int co = 8 * j + 2 * lane;
            size_t pi = ((size_t)(km * 64 + co) * B_ + b) * NBMAX_ + bx * 8 + w;
            psum[pi] = s0; psq[pi] = q0;
            pi = ((size_t)(km * 64 + co + 1) * B_ + b) * NBMAX_ + bx * 8 + w;
            psum[pi] = s1; psq[pi] = q1;
        }
    }

    // stage to smem (X/W regions are dead) then coalesced store
    __syncthreads();
    float* sd = reinterpret_cast<float*>(smem + w * 4416);   // 16 x 69 floats
    int r = lane >> 2, c = 2 * (lane & 3);
#pragma unroll
    for (int j = 0; j < 8; j++) {
        sd[r * 69 + 8 * j + c] = acc[j][0];
        sd[r * 69 + 8 * j + c + 1] = acc[j][1];
        sd[(r + 8) * 69 + 8 * j + c] = acc[j][2];
        sd[(r + 8) * 69 + 8 * j + c + 1] = acc[j][3];
    }
    __syncwarp();
    float* outb = out + (((size_t)km * B_ + b) * 64) * T_;
    int tt = lane & 15, cop = lane >> 4;
#pragma unroll
    for (int co2 = 0; co2 < 64; co2 += 2) {
        int co = co2 + cop;
        outb[(size_t)co * T_ + t0 + m0 + tt] = sd[tt * 69 + co];
    }
}

// ---- 4. BN stats finalize ----
__global__ __launch_bounds__(256) void stats_fin_kernel(int Cout, int nblk) {
    int co = blockIdx.x, km = blockIdx.y, tid = threadIdx.x;
    const float* ps = d_psum + (size_t)(km * Cout + co) * B_ * (co >= 0 ? 0 : 0);
    // note: partial layouts differ: conv1 uses stride NB=8; mma convs use NBMAX_.
    // nblk parameter selects the stride AND count.
    ps = d_psum + (size_t)(km * Cout + co) * B_ * nblk;
    const float* pq = d_psq + (size_t)(km * Cout + co) * B_ * nblk;
    float s = 0.f, q = 0.f;
    for (int i = tid; i < B_ * nblk; i += 256) { s += ps[i]; q += pq[i]; }
    __shared__ float r1[256], r2[256];
    r1[tid] = s; r2[tid] = q;
    __syncthreads();
    for (int o = 128; o > 0; o >>= 1) {
        if (tid < o) { r1[tid] += r1[tid + o]; r2[tid] += r2[tid + o]; }
        __syncthreads();
    }
    if (tid == 0) {
        float cnt = (float)B_ * (float)T_;
        float m = r1[0] / cnt;
        float v = r2[0] / cnt - m * m;
        d_mean[km * 64 + co] = m;
        d_rstd[km * 64 + co] = rsqrtf(v + EPS_);
    }
}

// ---- 5. pool ----
__global__ __launch_bounds__(256) void pool_kernel(
    const float* __restrict__ h, const float* __restrict__ bng,
    const float* __restrict__ bnb) {
    int co = blockIdx.x, b = blockIdx.y, km = blockIdx.z, tid = threadIdx.x;
    float a = bng[km * FEAT_ + co] * d_rstd[km * 64 + co];
    float cc = bnb[km * FEAT_ + co] - a * d_mean[km * 64 + co];
    const float* row = h + (((size_t)km * B_ + b) * FEAT_ + co) * T_;
    float s = 0.f;
    for (int t = tid; t < T_; t += 256)
        s += fmaxf(fmaf(a, row[t], cc), 0.f);
    __shared__ float r[256];
    r[tid] = s;
    __syncthreads();
    for (int o = 128; o > 0; o >>= 1) {
        if (tid < o) r[tid] += r[tid + o];
        __syncthreads();
    }
    if (tid == 0)
        d_feats[(size_t)b * (K_ * FEAT_) + km * FEAT_ + co] = r[0] * (1.0f / T_);
}

// ---- 6. classifier ----
__global__ __launch_bounds__(128) void classifier_kernel(
    const float* __restrict__ w1, const float* __restrict__ b1,
    const float* __restrict__ w2, const float* __restrict__ b2,
    float* __restrict__ out) {
    int b = blockIdx.x, j = threadIdx.x;
    __shared__ float sf[K_ * FEAT_];
    __shared__ float sh[HID_];
    for (int i = j; i < K_ * FEAT_; i += 128)
        sf[i] = d_feats[(size_t)b * (K_ * FEAT_) + i];
    __syncthreads();
    float a = b1[j];
    const float* wr = w1 + (size_t)j * (K_ * FEAT_);
#pragma unroll 8
    for (int i = 0; i < K_ * FEAT_; i++) a = fmaf(sf[i], wr[i], a);
    sh[j] = fmaxf(a, 0.f);
    __syncthreads();
    if (j < NCLS_) {
        float o = b2[j];
        const float* w2r = w2 + (size_t)j * HID_;
#pragma unroll 8
        for (int i = 0; i < HID_; i++) o = fmaf(sh[i], w2r[i], o);
        out[b * NCLS_ + j] = o;
    }
}

// ---- launch ----
extern "C" void kernel_launch(void* const* d_in, const int* in_sizes, int n_in,
                              void* d_out, int out_size) {
    const float* x         = (const float*)d_in[0];
    const float* log_alpha = (const float*)d_in[1];
    const float* raw_tau   = (const float*)d_in[2];
    const float* raw_omega = (const float*)d_in[3];
    const float* conv_w1   = (const float*)d_in[4];
    const float* conv_b1   = (const float*)d_in[5];
    const float* bn_g1     = (const float*)d_in[6];
    const float* bn_b1     = (const float*)d_in[7];
    const float* conv_w2   = (const float*)d_in[8];
    const float* conv_b2   = (const float*)d_in[9];
    const float* bn_g2     = (const float*)d_in[10];
    const float* bn_b2     = (const float*)d_in[11];
    const float* conv_w3   = (const float*)d_in[12];
    const float* conv_b3   = (const float*)d_in[13];
    const float* bn_g3     = (const float*)d_in[14];
    const float* bn_b3     = (const float*)d_in[15];
    const float* fc1_w     = (const float*)d_in[16];
    const float* fc1_b     = (const float*)d_in[17];
    const float* fc2_w     = (const float*)d_in[18];
    const float* fc2_b     = (const float*)d_in[19];
    float* out = (float*)d_out;

    float *p_modes, *p_h1, *p_h2, *p_h3, *p_psum, *p_psq;
    ull* p_w21;
    __nv_bfloat16 *p_wi2, *p_wi3;
    cudaGetSymbolAddress((void**)&p_modes, d_modes);
    cudaGetSymbolAddress((void**)&p_h1, d_h1);
    cudaGetSymbolAddress((void**)&p_h2, d_h2);
    cudaGetSymbolAddress((void**)&p_h3, d_h3);
    cudaGetSymbolAddress((void**)&p_psum, d_psum);
    cudaGetSymbolAddress((void**)&p_psq, d_psq);
    cudaGetSymbolAddress((void**)&p_w21, d_w2_1);
    cudaGetSymbolAddress((void**)&p_wi2, d_wimg2);
    cudaGetSymbolAddress((void**)&p_wi3, d_wimg3);

    // smem: 2*X + W + 2*CIN floats
    const int smem2 = 2 * 136 * 80 + 5 * 2 * 64 * 80 + 2 * 32 * 4;   // 73216
    const int smem3 = 2 * 136 * 144 + 3 * 2 * 64 * 144 + 2 * 64 * 4; // 94976
    cudaFuncSetAttribute(conv_mma_kernel<32, 5>,
                         cudaFuncAttributeMaxDynamicSharedMemorySize, smem2);
    cudaFuncSetAttribute(conv_mma_kernel<64, 3>,
                         cudaFuncAttributeMaxDynamicSharedMemorySize, smem3);

    g_kernel<<<(TR_ + 127) / 128, 128>>>(log_alpha, raw_tau, raw_omega);
    uvmd_kernel<<<B_ * C_, 256>>>(x);
    wprep_kernel<<<(K_ * 3 * 2 * 64 * 72 + 255) / 256, 256>>>(conv_w1, conv_w2, conv_w3);

    // conv1: CUDA core, CO=4, G=32 (TILE=256, NB=8)
    conv_kernel<12, 32, 7, 4, 32, 8><<<dim3(8, B_, K_), 256>>>(
        p_modes, p_w21, conv_b1, p_h1, p_psum, p_psq);
    stats_fin_kernel<<<dim3(32, K_), 256>>>(32, 8);
    // conv2: mma.sync (consumes BN1 stats)
    conv_mma_kernel<32, 5><<<dim3(16, B_, K_), 256, smem2>>>(
        p_h1, p_wi2, conv_b2, bn_g1, bn_b1, p_h2, p_psum, p_psq);
    stats_fin_kernel<<<dim3(64, K_), 256>>>(64, NBMAX_);
    // conv3: mma.sync (consumes BN2 stats)
    conv_mma_kernel<64, 3><<<dim3(16, B_, K_), 256, smem3>>>(
        p_h2, p_wi3, conv_b3, bn_g2, bn_b2, p_h3, p_psum, p_psq);
    stats_fin_kernel<<<dim3(64, K_), 256>>>(64, NBMAX_);
    pool_kernel<<<dim3(FEAT_, B_, K_), 256>>>(p_h3, bn_g3, bn_b3);
    classifier_kernel<<<B_, HID_>>>(fc1_w, fc1_b, fc2_w, fc2_b, out);
}

// round 14
// speedup vs baseline: 1.7951x; 1.2748x over previous
#include <cuda_runtime.h>
#include <cuda_bf16.h>
#include <math.h>
#include <stdint.h>

#define B_ 256
#define T_ 2048
#define C_ 12
#define K_ 4
#define L_ 8
#define FEAT_ 64
#define HID_ 128
#define NCLS_ 10
#define N2_ 1024
#define TR_ 1025
#define EPS_ 1e-5f
#define NBMAX_ 128

typedef unsigned long long ull;

__device__ float g_filt[K_ * TR_];
__device__ float d_modes[(size_t)K_ * B_ * C_ * T_];
__device__ float d_h1[(size_t)K_ * B_ * 32 * T_];
__device__ float d_h2[(size_t)K_ * B_ * 64 * T_];
__device__ float d_h3[(size_t)K_ * B_ * 64 * T_];
__device__ float d_psum[(size_t)K_ * 64 * B_ * NBMAX_];
__device__ float d_psq[(size_t)K_ * 64 * B_ * NBMAX_];
__device__ float d_mean[K_ * 64];
__device__ float d_rstd[K_ * 64];
__device__ float d_feats[B_ * K_ * FEAT_];
// mma weight images: [km][dk][half][co][ci padded to CINP] bf16 (hi,lo)
__device__ __align__(16) __nv_bfloat16 d_wimg1[K_ * 7 * 2 * 32 * 24];
__device__ __align__(16) __nv_bfloat16 d_wimg2[K_ * 5 * 2 * 64 * 40];
__device__ __align__(16) __nv_bfloat16 d_wimg3[K_ * 3 * 2 * 64 * 72];

__device__ __forceinline__ uint32_t smem_u32(const void* p) {
    uint32_t a;
    asm("{ .reg .u64 t; cvta.to.shared.u64 t, %1; cvt.u32.u64 %0, t; }" : "=r"(a) : "l"(p));
    return a;
}
__device__ __forceinline__ void ldsm4(uint32_t* a, uint32_t addr) {
    asm volatile("ldmatrix.sync.aligned.m8n8.x4.shared.b16 {%0,%1,%2,%3}, [%4];"
        : "=r"(a[0]), "=r"(a[1]), "=r"(a[2]), "=r"(a[3]) : "r"(addr));
}
__device__ __forceinline__ void ldsm2(uint32_t* b, uint32_t addr) {
    asm volatile("ldmatrix.sync.aligned.m8n8.x2.shared.b16 {%0,%1}, [%2];"
        : "=r"(b[0]), "=r"(b[1]) : "r"(addr));
}
__device__ __forceinline__ void mma16816(float* d, const uint32_t* a, const uint32_t* b) {
    asm volatile(
        "mma.sync.aligned.m16n8k16.row.col.f32.bf16.bf16.f32 "
        "{%0,%1,%2,%3}, {%4,%5,%6,%7}, {%8,%9}, {%0,%1,%2,%3};"
        : "+f"(d[0]), "+f"(d[1]), "+f"(d[2]), "+f"(d[3])
        : "r"(a[0]), "r"(a[1]), "r"(a[2]), "r"(a[3]), "r"(b[0]), "r"(b[1]));
}

// ---- 1. UVMD filters ----
__device__ __forceinline__ float softplusf(float x) {
    if (x > 20.f) return x;
    return log1pf(expf(x));
}
__global__ __launch_bounds__(128) void g_kernel(
        const float* __restrict__ la, const float* __restrict__ rt,
        const float* __restrict__ ro) {
    float om[K_];
#pragma unroll
    for (int k = 0; k < K_; k++) om[k] = 0.5f / (1.0f + expf(-ro[k]));
    int f = blockIdx.x * blockDim.x + threadIdx.x;
    if (f >= TR_) return;
    float fr = 0.5f * (float)f / 1024.0f;
    float u[K_] = {0.f, 0.f, 0.f, 0.f};
    float lam = 0.f;
    for (int l = 0; l < L_; l++) {
        float tau_l = softplusf(rt[l]);
        float us = u[0] + u[1] + u[2] + u[3];
        float nu[K_], ns = 0.f;
#pragma unroll
        for (int k = 0; k < K_; k++) {
            float a = expf(la[l * K_ + k]);
            float d = fr - om[k];
            nu[k] = (1.0f - (us - u[k]) + 0.5f * lam) / (1.0f + 2.0f * a * d * d);
            ns += nu[k];
        }
#pragma unroll
        for (int k = 0; k < K_; k++) u[k] = nu[k];
        lam += tau_l * (1.0f - ns);
    }
#pragma unroll
    for (int k = 0; k < K_; k++) g_filt[k * TR_ + f] = u[k];
}

// ---- 2. UVMD FFT ----
__device__ __forceinline__ void fft1024(float* zr, float* zi, const float* twr,
                                        const float* twi, float dir, int tid) {
#pragma unroll
    for (int s = 0; s < 10; s++) {
        int half = 1 << s, shift = 9 - s;
#pragma unroll
        for (int rep = 0; rep < 2; rep++) {
            int i = tid + rep * 256;
            int pos = i & (half - 1);
            int i1 = ((i >> s) << (s + 1)) + pos;
            int i2 = i1 + half;
            int ti = pos << shift;
            float c = twr[ti], sn = dir * twi[ti];
            float x2r = zr[i2], x2i = zi[i2];
            float tr = c * x2r - sn * x2i, tim = sn * x2r + c * x2i;
            float x1r = zr[i1], x1i = zi[i1];
            zr[i2] = x1r - tr; zi[i2] = x1i - tim;
            zr[i1] = x1r + tr; zi[i1] = x1i + tim;
        }
        __syncthreads();
    }
}
__global__ __launch_bounds__(256) void uvmd_kernel(const float* __restrict__ x) {
    __shared__ float twr[512], twi[512];
    __shared__ float zr[N2_], zi[N2_];
    __shared__ float Xr[TR_], Xi[TR_];
    int tid = threadIdx.x;
    int b = blockIdx.x / C_, c = blockIdx.x % C_;
    for (int j = tid; j < 512; j += 256) {
        float ang = (float)M_PI * (float)j / 512.0f;
        twr[j] = cosf(ang); twi[j] = -sinf(ang);
    }
    const float* xb = x + (size_t)b * T_ * C_ + c;
    for (int n = tid; n < N2_; n += 256) {
        int j = __brev((unsigned)n) >> 22;
        zr[n] = xb[(size_t)(2 * j) * C_];
        zi[n] = xb[(size_t)(2 * j + 1) * C_];
    }
    __syncthreads();
    fft1024(zr, zi, twr, twi, 1.0f, tid);
    for (int k = tid; k < N2_; k += 256) {
        if (k == 0) {
            Xr[0] = zr[0] + zi[0]; Xi[0] = 0.f;
            Xr[N2_] = zr[0] - zi[0]; Xi[N2_] = 0.f;
        } else {
            float ar = zr[k], ai = zi[k];
            float br = zr[N2_ - k], bi = -zi[N2_ - k];
            float er = 0.5f * (ar + br), ei = 0.5f * (ai + bi);
            float dr = 0.5f * (ar - br), di = 0.5f * (ai - bi);
            float or_ = di, oi = -dr, s_, c_;
            __sincosf(-(float)M_PI * (float)k / 1024.0f, &s_, &c_);
            Xr[k] = er + c_ * or_ - s_ * oi;
            Xi[k] = ei + s_ * or_ + c_ * oi;
        }
    }
    __syncthreads();
    const float invn = 1.0f / 1024.0f;
    for (int km = 0; km < K_; km++) {
        const float* g = g_filt + km * TR_;
        for (int n = tid; n < N2_; n += 256) {
            int k = __brev((unsigned)n) >> 22;
            float vr, vi;
            if (k == 0) {
                float y0 = g[0] * Xr[0], y1 = g[N2_] * Xr[N2_];
                vr = 0.5f * (y0 + y1); vi = 0.5f * (y0 - y1);
            } else {
                float gk = g[k], gm = g[N2_ - k];
                float yr = gk * Xr[k], yi = gk * Xi[k];
                float mr = gm * Xr[N2_ - k], mi = -(gm * Xi[N2_ - k]);
                float er = 0.5f * (yr + mr), ei = 0.5f * (yi + mi);
                float dr = 0.5f * (yr - mr), di = 0.5f * (yi - mi);
                float s_, c_;
                __sincosf((float)M_PI * (float)k / 1024.0f, &s_, &c_);
                vr = er - (s_ * dr + c_ * di);
                vi = ei + (c_ * dr - s_ * di);
            }
            zr[n] = vr; zi[n] = vi;
        }
        __syncthreads();
        fft1024(zr, zi, twr, twi, -1.0f, tid);
        float* orow = d_modes + ((((size_t)km * B_ + b) * C_ + c)) * T_;
        for (int n = tid; n < N2_; n += 256)
            *reinterpret_cast<float2*>(orow + 2 * n) =
                make_float2(zr[n] * invn, zi[n] * invn);
        __syncthreads();
    }
}

// ---- 2b. weight prep: hi/lo split, padded [km][dk][half][co][ciP] ----
template <int CIN, int KS, int CINP, int COUT>
__device__ __forceinline__ void wimg_one(const float* __restrict__ w,
                                         __nv_bfloat16* __restrict__ img, int i) {
    const int n = K_ * KS * 2 * COUT * CINP;
    if (i >= n) return;
    int ci = i % CINP;
    int r = i / CINP;
    int co = r % COUT; r /= COUT;
    int half = r % 2; r /= 2;
    int dk = r % KS;
    int km = r / KS;
    float f = (ci < CIN) ? w[(((size_t)km * COUT + co) * CIN + ci) * KS + dk] : 0.f;
    __nv_bfloat16 hi = __float2bfloat16(f);
    img[i] = half ? __float2bfloat16(f - __bfloat162float(hi)) : hi;
}
__global__ __launch_bounds__(256) void wprep_kernel(
    const float* __restrict__ w1, const float* __restrict__ w2,
    const float* __restrict__ w3) {
    int i = blockIdx.x * blockDim.x + threadIdx.x;
    wimg_one<12, 7, 24, 32>(w1, d_wimg1, i);
    wimg_one<32, 5, 40, 64>(w2, d_wimg2, i);
    wimg_one<64, 3, 72, 64>(w3, d_wimg3, i);
}

// ---- 3. conv via mma.sync bf16 hi/lo split; NT tiles per CTA ----
// CTA = NT consecutive 128t tiles x COUT for one (km,b). 8 warps; warp w
// owns t rows 16w..16w+15 x all COUT (NFR n-frags of m16n8k16).
template <int CIN, int COUT, int KS, int NT, bool HASBN>
__global__ __launch_bounds__(256) void conv_mma_kernel(
    const float* __restrict__ in, const __nv_bfloat16* __restrict__ wimg,
    const float* __restrict__ bias,
    const float* __restrict__ bng, const float* __restrict__ bnb,
    float* __restrict__ out, float* __restrict__ psum, float* __restrict__ psq)
{
    constexpr int PAD = KS / 2, NROW = 136;
    constexpr int CIN16 = ((CIN + 15) / 16) * 16;
    constexpr int CINP = CIN16 + 8, ROWB = CINP * 2;
    constexpr int XB = NROW * ROWB, WSEG = COUT * ROWB;
    constexpr int OFF_XL = XB, OFF_W = 2 * XB;
    constexpr int STR = COUT + 5;
    constexpr int OFF_STG = OFF_W + KS * 2 * WSEG;
    constexpr int OFF_SA = OFF_STG + 8 * 8 * STR * 4;
    constexpr int NCC = CIN16 / 16, NFR = COUT / 8;
    constexpr int NBP = (16 / NT) * 8;       // stats partials per (co,b)
    extern __shared__ __align__(16) char smem[];
    uint32_t sb = smem_u32(smem);
    int tid = threadIdx.x, w = tid >> 5, lane = tid & 31;
    int b = blockIdx.y, km = blockIdx.z, bx = blockIdx.x;

    float* s_a = reinterpret_cast<float*>(smem + OFF_SA);
    float* s_c = s_a + CIN;
    if (HASBN) {
        for (int ci = tid; ci < CIN; ci += 256) {
            float a = bng[km * CIN + ci] * d_rstd[km * 64 + ci];
            s_a[ci] = a;
            s_c[ci] = bnb[km * CIN + ci] - a * d_mean[km * 64 + ci];
        }
    }
    {   // W copy once per CTA
        const uint4* src = reinterpret_cast<const uint4*>(
            reinterpret_cast<const char*>(wimg) + (size_t)km * KS * 2 * WSEG);
        uint4* dst = reinterpret_cast<uint4*>(smem + OFF_W);
        for (int i = tid; i < KS * 2 * WSEG / 16; i += 256) dst[i] = src[i];
    }
    __syncthreads();

    const float* inb = in + (((size_t)km * B_ + b) * CIN) * T_;
    float* outb = out + (((size_t)km * B_ + b) * COUT) * T_;
    int m0 = w * 16;
    uint32_t aoff = (uint32_t)((lane & 15) * ROWB + (lane >> 4) * 16);
    uint32_t boff = (uint32_t)((lane & 7) * ROWB + ((lane >> 3) & 1) * 16);
    int cbase = 2 * (lane & 3);
    float bb0[NFR], bb1[NFR];
#pragma unroll
    for (int j = 0; j < NFR; j++) {
        bb0[j] = __ldg(&bias[km * COUT + 8 * j + cbase]);
        bb1[j] = __ldg(&bias[km * COUT + 8 * j + cbase + 1]);
    }
    float sth0[NFR], sth1[NFR], qth0[NFR], qth1[NFR];
#pragma unroll
    for (int j = 0; j < NFR; j++) { sth0[j] = sth1[j] = qth0[j] = qth1[j] = 0.f; }

    for (int tile = 0; tile < NT; tile++) {
        int t0 = (bx * NT + tile) * 128;
        // X fill: (BN+ReLU) + hi/lo split; rows r = local t; pad ci zeroed
        for (int idx = tid; idx < CIN16 * NROW; idx += 256) {
            int ci = idx / NROW, r = idx - ci * NROW;
            int t = t0 + r - PAD;
            float v = 0.f;
            if (ci < CIN && t >= 0 && t < T_) {
                v = inb[(size_t)ci * T_ + t];
                if (HASBN) v = fmaxf(fmaf(s_a[ci], v, s_c[ci]), 0.f);
            }
            __nv_bfloat16 hi = __float2bfloat16(v);
            __nv_bfloat16 lo = __float2bfloat16(v - __bfloat162float(hi));
            *reinterpret_cast<__nv_bfloat16*>(smem + r * ROWB + ci * 2) = hi;
            *reinterpret_cast<__nv_bfloat16*>(smem + OFF_XL + r * ROWB + ci * 2) = lo;
        }
        __syncthreads();

        float acc[NFR][4];
#pragma unroll
        for (int j = 0; j < NFR; j++)
#pragma unroll
            for (int p = 0; p < 4; p++) acc[j][p] = 0.f;
#pragma unroll
        for (int cc = 0; cc < NCC; cc++) {
#pragma unroll
            for (int dk = 0; dk < KS; dk++) {
                uint32_t ab = sb + (uint32_t)((m0 + dk) * ROWB + cc * 32) + aoff;
                uint32_t ah[4], al[4];
                ldsm4(ah, ab);
                ldsm4(al, ab + XB);
                uint32_t wbase = sb + OFF_W + (uint32_t)(dk * 2 * WSEG + cc * 32) + boff;
#pragma unroll
                for (int j = 0; j < NFR; j++) {
                    uint32_t bh[2], bl[2];
                    ldsm2(bh, wbase + j * 8 * ROWB);
                    ldsm2(bl, wbase + WSEG + j * 8 * ROWB);
                    mma16816(acc[j], ah, bh);
                    mma16816(acc[j], ah, bl);
                    mma16816(acc[j], al, bh);
                }
            }
        }
        __syncthreads();   // all ldmatrix done; X safe to refill next tile

        // bias + stats accumulate + staged store (2 rounds of 8 t-rows)
        float* sd = reinterpret_cast<float*>(smem + OFF_STG) + w * 8 * STR;
        int r = lane >> 2;
#pragma unroll
        for (int p = 0; p < 2; p++) {
#pragma unroll
            for (int j = 0; j < NFR; j++) {
                float v0 = acc[j][2 * p] + bb0[j];
                float v1 = acc[j][2 * p + 1] + bb1[j];
                sth0[j] += v0; sth1[j] += v1;
                qth0[j] += v0 * v0; qth1[j] += v1 * v1;
                sd[r * STR + 8 * j + cbase] = v0;
                sd[r * STR + 8 * j + cbase + 1] = v1;
            }
            __syncwarp();
            int tt = lane & 7, cop = lane >> 3;
#pragma unroll
            for (int co2 = 0; co2 < COUT; co2 += 4) {
                int co = co2 + cop;
                outb[(size_t)co * T_ + t0 + m0 + 8 * p + tt] = sd[tt * STR + co];
            }
            __syncwarp();
        }
    }

    // final stats reduce + write
#pragma unroll
    for (int j = 0; j < NFR; j++) {
        float s0 = sth0[j], s1 = sth1[j], q0 = qth0[j], q1 = qth1[j];
#pragma unroll
        for (int o = 16; o >= 4; o >>= 1) {
            s0 += __shfl_down_sync(0xffffffffu, s0, o);
            s1 += __shfl_down_sync(0xffffffffu, s1, o);
            q0 += __shfl_down_sync(0xffffffffu, q0, o);
            q1 += __shfl_down_sync(0xffffffffu, q1, o);
        }
        if (lane < 4) {
            int co = 8 * j + 2 * lane;
            size_t pi = ((size_t)(km * COUT + co) * B_ + b) * NBP + bx * 8 + w;
            psum[pi] = s0; psq[pi] = q0;
            pi = ((size_t)(km * COUT + co + 1) * B_ + b) * NBP + bx * 8 + w;
            psum[pi] = s1; psq[pi] = q1;
        }
    }
}

// ---- 4. BN stats finalize ----
__global__ __launch_bounds__(256) void stats_fin_kernel(int Cout, int nblk) {
    int co = blockIdx.x, km = blockIdx.y, tid = threadIdx.x;
    const float* ps = d_psum + (size_t)(km * Cout + co) * B_ * nblk;
    const float* pq = d_psq + (size_t)(km * Cout + co) * B_ * nblk;
    float s = 0.f, q = 0.f;
    for (int i = tid; i < B_ * nblk; i += 256) { s += ps[i]; q += pq[i]; }
    __shared__ float r1[256], r2[256];
    r1[tid] = s; r2[tid] = q;
    __syncthreads();
    for (int o = 128; o > 0; o >>= 1) {
        if (tid < o) { r1[tid] += r1[tid + o]; r2[tid] += r2[tid + o]; }
        __syncthreads();
    }
    if (tid == 0) {
        float cnt = (float)B_ * (float)T_;
        float m = r1[0] / cnt;
        float v = r2[0] / cnt - m * m;
        d_mean[km * 64 + co] = m;
        d_rstd[km * 64 + co] = rsqrtf(v + EPS_);
    }
}

// ---- 5. pool ----
__global__ __launch_bounds__(256) void pool_kernel(
    const float* __restrict__ h, const float* __restrict__ bng,
    const float* __restrict__ bnb) {
    int co = blockIdx.x, b = blockIdx.y, km = blockIdx.z, tid = threadIdx.x;
    float a = bng[km * FEAT_ + co] * d_rstd[km * 64 + co];
    float cc = bnb[km * FEAT_ + co] - a * d_mean[km * 64 + co];
    const float* row = h + (((size_t)km * B_ + b) * FEAT_ + co) * T_;
    float s = 0.f;
    for (int t = tid; t < T_; t += 256)
        s += fmaxf(fmaf(a, row[t], cc), 0.f);
    __shared__ float r[256];
    r[tid] = s;
    __syncthreads();
    for (int o = 128; o > 0; o >>= 1) {
        if (tid < o) r[tid] += r[tid + o];
        __syncthreads();
    }
    if (tid == 0)
        d_feats[(size_t)b * (K_ * FEAT_) + km * FEAT_ + co] = r[0] * (1.0f / T_);
}

// ---- 6. classifier ----
__global__ __launch_bounds__(128) void classifier_kernel(
    const float* __restrict__ w1, const float* __restrict__ b1,
    const float* __restrict__ w2, const float* __restrict__ b2,
    float* __restrict__ out) {
    int b = blockIdx.x, j = threadIdx.x;
    __shared__ float sf[K_ * FEAT_];
    __shared__ float sh[HID_];
    for (int i = j; i < K_ * FEAT_; i += 128)
        sf[i] = d_feats[(size_t)b * (K_ * FEAT_) + i];
    __syncthreads();
    float a = b1[j];
    const float* wr = w1 + (size_t)j * (K_ * FEAT_);
#pragma unroll 8
    for (int i = 0; i < K_ * FEAT_; i++) a = fmaf(sf[i], wr[i], a);
    sh[j] = fmaxf(a, 0.f);
    __syncthreads();
    if (j < NCLS_) {
        float o = b2[j];
        const float* w2r = w2 + (size_t)j * HID_;
#pragma unroll 8
        for (int i = 0; i < HID_; i++) o = fmaf(sh[i], w2r[i], o);
        out[b * NCLS_ + j] = o;
    }
}

// ---- launch ----
extern "C" void kernel_launch(void* const* d_in, const int* in_sizes, int n_in,
                              void* d_out, int out_size) {
    const float* x         = (const float*)d_in[0];
    const float* log_alpha = (const float*)d_in[1];
    const float* raw_tau   = (const float*)d_in[2];
    const float* raw_omega = (const float*)d_in[3];
    const float* conv_w1   = (const float*)d_in[4];
    const float* conv_b1   = (const float*)d_in[5];
    const float* bn_g1     = (const float*)d_in[6];
    const float* bn_b1     = (const float*)d_in[7];
    const float* conv_w2   = (const float*)d_in[8];
    const float* conv_b2   = (const float*)d_in[9];
    const float* bn_g2     = (const float*)d_in[10];
    const float* bn_b2     = (const float*)d_in[11];
    const float* conv_w3   = (const float*)d_in[12];
    const float* conv_b3   = (const float*)d_in[13];
    const float* bn_g3     = (const float*)d_in[14];
    const float* bn_b3     = (const float*)d_in[15];
    const float* fc1_w     = (const float*)d_in[16];
    const float* fc1_b     = (const float*)d_in[17];
    const float* fc2_w     = (const float*)d_in[18];
    const float* fc2_b     = (const float*)d_in[19];
    float* out = (float*)d_out;

    float *p_modes, *p_h1, *p_h2, *p_h3, *p_psum, *p_psq;
    __nv_bfloat16 *p_wi1, *p_wi2, *p_wi3;
    cudaGetSymbolAddress((void**)&p_modes, d_modes);
    cudaGetSymbolAddress((void**)&p_h1, d_h1);
    cudaGetSymbolAddress((void**)&p_h2, d_h2);
    cudaGetSymbolAddress((void**)&p_h3, d_h3);
    cudaGetSymbolAddress((void**)&p_psum, d_psum);
    cudaGetSymbolAddress((void**)&p_psq, d_psq);
    cudaGetSymbolAddress((void**)&p_wi1, d_wimg1);
    cudaGetSymbolAddress((void**)&p_wi2, d_wimg2);
    cudaGetSymbolAddress((void**)&p_wi3, d_wimg3);

    // smem sizes: 2*XB + KS*2*WSEG + STG(8*8*STR*4) + coeffs
    const int smem1 = 2 * 136 * 48 + 7 * 2 * 32 * 48 + 8 * 8 * 37 * 4 + 128;
    const int smem2 = 2 * 136 * 80 + 5 * 2 * 64 * 80 + 8 * 8 * 69 * 4 + 256;
    const int smem3 = 2 * 136 * 144 + 3 * 2 * 64 * 144 + 8 * 8 * 69 * 4 + 512;
    cudaFuncSetAttribute((const void*)conv_mma_kernel<12, 32, 7, 8, false>,
                         cudaFuncAttributeMaxDynamicSharedMemorySize, smem1);
    cudaFuncSetAttribute((const void*)conv_mma_kernel<32, 64, 5, 8, true>,
                         cudaFuncAttributeMaxDynamicSharedMemorySize, smem2);
    cudaFuncSetAttribute((const void*)conv_mma_kernel<64, 64, 3, 8, true>,
                         cudaFuncAttributeMaxDynamicSharedMemorySize, smem3);

    g_kernel<<<(TR_ + 127) / 128, 128>>>(log_alpha, raw_tau, raw_omega);
    uvmd_kernel<<<B_ * C_, 256>>>(x);
    wprep_kernel<<<(K_ * 3 * 2 * 64 * 72 + 255) / 256, 256>>>(conv_w1, conv_w2, conv_w3);

    // conv1: mma, no input BN  <-- ncu capture (#4)
    conv_mma_kernel<12, 32, 7, 8, false><<<dim3(2, B_, K_), 256, smem1>>>(
        p_modes, p_wi1, conv_b1, nullptr, nullptr, p_h1, p_psum, p_psq);
    stats_fin_kernel<<<dim3(32, K_), 256>>>(32, 16);
    // conv2: mma, BN1+ReLU fused on input
    conv_mma_kernel<32, 64, 5, 8, true><<<dim3(2, B_, K_), 256, smem2>>>(
        p_h1, p_wi2, conv_b2, bn_g1, bn_b1, p_h2, p_psum, p_psq);
    stats_fin_kernel<<<dim3(64, K_), 256>>>(64, 16);
    // conv3: mma, BN2+ReLU fused on input
    conv_mma_kernel<64, 64, 3, 8, true><<<dim3(2, B_, K_), 256, smem3>>>(
        p_h2, p_wi3, conv_b3, bn_g2, bn_b2, p_h3, p_psum, p_psq);
    stats_fin_kernel<<<dim3(64, K_), 256>>>(64, 16);
    pool_kernel<<<dim3(FEAT_, B_, K_), 256>>>(p_h3, bn_g3, bn_b3);
    classifier_kernel<<<B_, HID_>>>(fc1_w, fc1_b, fc2_w, fc2_b, out);
}